// round 8
// baseline (speedup 1.0000x reference)
#include <cuda_runtime.h>
#include <cuda_fp16.h>
#include <math.h>
#include <stdint.h>

// Problem constants
#define BATCH 2
#define SEQ   1024
#define DM    1024
#define NH    64
#define NHK   8
#define HD    64
#define WIN   128
#define GQA   8
#define QKV_N 5120
#define K_OFF 4096
#define V_OFF 4608

// Scratch (device globals)
__device__ __align__(16) float  g_qkv[BATCH * SEQ * QKV_N];
__device__ __align__(16) __half g_xh[BATCH * SEQ * DM];
__device__ __align__(16) __half g_wqh[NH * HD * DM];
__device__ __align__(16) __half g_wkh[NHK * HD * DM];
__device__ __align__(16) __half g_wvh[NHK * HD * DM];
__device__ __align__(16) __half g_woh[DM * NH * HD];
__device__ __align__(16) __half g_attnh[BATCH * SEQ * NH * HD];

// ---------------------------------------------------------------------------
// helpers
// ---------------------------------------------------------------------------
__device__ __forceinline__ unsigned f2tf32(float x) {
    unsigned u;
    asm("cvt.rna.tf32.f32 %0, %1;" : "=r"(u) : "f"(x));
    return u;
}
__device__ __forceinline__ unsigned pack_h2(float a, float b) {
    __half2 h = __floats2half2_rn(a, b);
    return *(unsigned*)&h;
}
__device__ __forceinline__ uint32_t smem_u32(const void* p) {
    uint32_t a;
    asm("{ .reg .u64 t; cvta.to.shared.u64 t, %1; cvt.u32.u64 %0, t; }" : "=r"(a) : "l"(p));
    return a;
}
#define CP16(dst, src) \
    asm volatile("cp.async.cg.shared.global [%0], [%1], 16;" \
        :: "r"(dst), "l"(__cvta_generic_to_global(src)))
#define CP_COMMIT() asm volatile("cp.async.commit_group;")
#define CP_WAIT(n)  asm volatile("cp.async.wait_group %0;" :: "n"(n))
#define LDSM_X4(r0, r1, r2, r3, addr) \
    asm volatile("ldmatrix.sync.aligned.m8n8.x4.shared.b16 {%0,%1,%2,%3}, [%4];" \
        : "=r"(r0), "=r"(r1), "=r"(r2), "=r"(r3) : "r"(addr))

__device__ __forceinline__ void mma_f16(float* c, const unsigned* a, const unsigned* b) {
    asm volatile(
        "mma.sync.aligned.m16n8k16.row.col.f32.f16.f16.f32 "
        "{%0,%1,%2,%3}, {%4,%5,%6,%7}, {%8,%9}, {%0,%1,%2,%3};"
        : "+f"(c[0]), "+f"(c[1]), "+f"(c[2]), "+f"(c[3])
        : "r"(a[0]), "r"(a[1]), "r"(a[2]), "r"(a[3]), "r"(b[0]), "r"(b[1]));
}
__device__ __forceinline__ void mma_tf32(float* c, const unsigned* a, const unsigned* b) {
    asm volatile(
        "mma.sync.aligned.m16n8k8.row.col.f32.tf32.tf32.f32 "
        "{%0,%1,%2,%3}, {%4,%5,%6,%7}, {%8,%9}, {%0,%1,%2,%3};"
        : "+f"(c[0]), "+f"(c[1]), "+f"(c[2]), "+f"(c[3])
        : "r"(a[0]), "r"(a[1]), "r"(a[2]), "r"(a[3]), "r"(b[0]), "r"(b[1]));
}

// ---------------------------------------------------------------------------
// fp32 -> fp16 conversion of x + all weights (one kernel)
// ---------------------------------------------------------------------------
#define CVT_TOTAL4 2883584
__global__ __launch_bounds__(256) void cvt_kernel(
    const float* __restrict__ x,  const float* __restrict__ wq,
    const float* __restrict__ wk, const float* __restrict__ wv,
    const float* __restrict__ wo)
{
    size_t i = (size_t)blockIdx.x * 256 + threadIdx.x;
    const float* src; __half* dst; size_t off;
    if (i < 524288)       { src = x;  dst = g_xh;  off = i; }
    else if (i < 1572864) { src = wq; dst = g_wqh; off = i - 524288; }
    else if (i < 1703936) { src = wk; dst = g_wkh; off = i - 1572864; }
    else if (i < 1835008) { src = wv; dst = g_wvh; off = i - 1703936; }
    else                  { src = wo; dst = g_woh; off = i - 1835008; }
    float4 v = ((const float4*)src)[off];
    ((uint2*)dst)[off] = make_uint2(pack_h2(v.x, v.y), pack_h2(v.z, v.w));
}

// ---------------------------------------------------------------------------
// FP16 GEMM core: cp.async 3-stage pipeline + ldmatrix fragment loads.
// C[128,128] tile = A[M,K](half) @ B[128,K](half)^T + bias(f32), C f32.
// Smem rows: 32 halves (4 x 16B chunks), chunk swizzle c ^ ((r>>1)&3).
// 256 threads = 8 warps, warp = 32(M) x 64(N). ONE syncthreads per K-step.
// ---------------------------------------------------------------------------
#define ST_WORDS 2048
#define B_BASE   6144

__device__ __forceinline__ void gemm_h_core(
    const __half* __restrict__ A, const __half* __restrict__ Bw,
    const float* __restrict__ bias, float* __restrict__ Cg,
    int K, int ldc, int by, int colbase)
{
    __shared__ uint32_t S[12288];   // 48KB: A[3][2048] + B[3][2048]

    const int tid  = threadIdx.x;
    const int wid  = tid >> 5;
    const int lane = tid & 31;
    const int wm   = wid & 3;
    const int wn   = wid >> 2;
    const int g    = lane >> 2;
    const int t    = lane & 3;

    const __half* Ag = A + (size_t)(by * 128) * K;

    // cp.async store geometry
    const int r  = tid >> 1;
    const int cb = (tid & 1) * 2;
    const int swst = (r >> 1) & 3;
    const uint32_t sb = smem_u32(S);
    const uint32_t ad0 = sb + r * 64 + (((cb + 0) ^ swst) << 4);
    const uint32_t ad1 = sb + r * 64 + (((cb + 1) ^ swst) << 4);
    const __half* arow = Ag + (size_t)r * K + cb * 8;
    const __half* brow = Bw + (size_t)r * K + cb * 8;

    // ldmatrix lane geometry
    const int lane15 = lane & 15;
    const int hiA = lane >> 4;                                  // A: chunk +hiA
    const int rowA0 = wm * 32 + lane15;                         // mt=0 rows
    const int rowA1 = rowA0 + 16;                               // mt=1 rows
    const int swA0 = (rowA0 >> 1) & 3, swA1 = (rowA1 >> 1) & 3;
    const int hiB = (lane >> 3) & 1;                            // B: chunk +hiB
    const int rowBb = wn * 64 + ((lane >> 4) & 1) * 8 + (lane & 7);
    // byte offsets (row*64) precomputed
    const uint32_t offA0 = (uint32_t)rowA0 * 64;
    const uint32_t offA1 = (uint32_t)rowA1 * 64;

    float acc[2][8][4];
#pragma unroll
    for (int mt = 0; mt < 2; mt++)
#pragma unroll
        for (int nt = 0; nt < 8; nt++)
#pragma unroll
            for (int i = 0; i < 4; i++) acc[mt][nt][i] = 0.0f;

    const int niter = K >> 5;

#pragma unroll
    for (int s = 0; s < 2; s++) {
        const uint32_t bo = s * 8192;
        CP16(ad0 + bo, arow + s * 32);
        CP16(ad1 + bo, arow + s * 32 + 8);
        CP16(ad0 + bo + 24576, brow + s * 32);
        CP16(ad1 + bo + 24576, brow + s * 32 + 8);
        CP_COMMIT();
    }

    for (int it = 0; it < niter; it++) {
        const int buf = it % 3;
        if (it + 1 < niter) { CP_WAIT(1); } else { CP_WAIT(0); }
        __syncthreads();

        // prefetch stage it+2 (buffer (it+2)%3: last read at iter it-1, safe)
        if (it + 2 < niter) {
            const int s = it + 2;
            const uint32_t bo = (s % 3) * 8192;
            CP16(ad0 + bo, arow + (size_t)s * 32);
            CP16(ad1 + bo, arow + (size_t)s * 32 + 8);
            CP16(ad0 + bo + 24576, brow + (size_t)s * 32);
            CP16(ad1 + bo + 24576, brow + (size_t)s * 32 + 8);
            CP_COMMIT();
        }

        const uint32_t sa  = sb + buf * 8192;
        const uint32_t sbb = sa + 24576;

#pragma unroll
        for (int kk = 0; kk < 2; kk++) {
            unsigned a[2][4], b[8][2];
            const int cA = 2 * kk + hiA;
            LDSM_X4(a[0][0], a[0][1], a[0][2], a[0][3], sa + offA0 + (((cA ^ swA0)) << 4));
            LDSM_X4(a[1][0], a[1][1], a[1][2], a[1][3], sa + offA1 + (((cA ^ swA1)) << 4));
            const int cB = 2 * kk + hiB;
#pragma unroll
            for (int p = 0; p < 4; p++) {
                const int rowB = rowBb + p * 16;
                const int swB = (rowB >> 1) & 3;
                LDSM_X4(b[2 * p][0], b[2 * p][1], b[2 * p + 1][0], b[2 * p + 1][1],
                        sbb + (uint32_t)rowB * 64 + (((cB ^ swB)) << 4));
            }
#pragma unroll
            for (int mt = 0; mt < 2; mt++)
#pragma unroll
                for (int nt = 0; nt < 8; nt++)
                    mma_f16(acc[mt][nt], a[mt], b[nt]);
        }
    }

    // epilogue with bias
#pragma unroll
    for (int mt = 0; mt < 2; mt++) {
        const int row0 = by * 128 + wm * 32 + mt * 16 + g;
#pragma unroll
        for (int nt = 0; nt < 8; nt++) {
            const int col = wn * 64 + nt * 8 + 2 * t;
            const float b0 = bias[col], b1 = bias[col + 1];
            float2 o0 = make_float2(acc[mt][nt][0] + b0, acc[mt][nt][1] + b1);
            float2 o1 = make_float2(acc[mt][nt][2] + b0, acc[mt][nt][3] + b1);
            *(float2*)(Cg + (size_t)row0 * ldc + colbase + col) = o0;
            *(float2*)(Cg + (size_t)(row0 + 8) * ldc + colbase + col) = o1;
        }
    }
}

// Merged QKV projection: grid.x in [0,40): 0-31 Q, 32-35 K, 36-39 V
__global__ __launch_bounds__(256, 2) void gemm_qkv(
    const float* __restrict__ bq, const float* __restrict__ bk,
    const float* __restrict__ bv, float* __restrict__ C)
{
    const int bx = blockIdx.x;
    const __half* W; const float* bias; int wt, seg;
    if (bx < 32)      { W = g_wqh; bias = bq; wt = bx;      seg = 0; }
    else if (bx < 36) { W = g_wkh; bias = bk; wt = bx - 32; seg = K_OFF; }
    else              { W = g_wvh; bias = bv; wt = bx - 36; seg = V_OFF; }
    gemm_h_core(g_xh, W + (size_t)wt * 128 * DM, bias + wt * 128,
                C, DM, QKV_N, blockIdx.y, seg + wt * 128);
}

// Output projection
__global__ __launch_bounds__(256, 2) void gemm_out(
    const float* __restrict__ bias, float* __restrict__ C)
{
    gemm_h_core(g_attnh, g_woh + (size_t)blockIdx.x * 128 * (NH * HD),
                bias + blockIdx.x * 128, C, NH * HD, DM, blockIdx.y, blockIdx.x * 128);
}

// ---------------------------------------------------------------------------
// Flash-style sliding-window GQA attention with sink logit (unchanged R7)
// ---------------------------------------------------------------------------
#define KC   32
#define KPAD 68
#define PPAD 36
#define KS_OFF 0
#define VS_OFF (KC * KPAD)
#define PS_OFF (2 * KC * KPAD)
#define ATTN_SMEM ((2 * KC * KPAD + 256 * PPAD) * 4)

__global__ __launch_bounds__(256) void attn_mma_kernel(
    const float* __restrict__ qkv, const float* __restrict__ sinks,
    __half* __restrict__ out)
{
    extern __shared__ unsigned asmem[];
    unsigned* Ks = asmem + KS_OFF;
    unsigned* Vs = asmem + VS_OFF;
    unsigned* Ps = asmem + PS_OFF;

    const int q0  = blockIdx.x * 32;
    const int hk  = blockIdx.y;
    const int b   = blockIdx.z;
    const int tid = threadIdx.x;
    const int wid = tid >> 5;
    const int lane = tid & 31;
    const int g = lane >> 2;
    const int t = lane & 3;

    const int kbase = (q0 >= 128) ? (q0 - 128) : 0;
    const int nch = (q0 + 32 - kbase) >> 5;

    unsigned qa[2][8][4];
    {
        const float* qrow = qkv + ((size_t)(b * SEQ + q0)) * QKV_N + hk * 512 + wid * 64;
#pragma unroll
        for (int mt = 0; mt < 2; mt++) {
            const float* r0 = qrow + (size_t)(mt * 16 + g) * QKV_N;
            const float* r1 = r0 + (size_t)8 * QKV_N;
#pragma unroll
            for (int k = 0; k < 8; k++) {
                qa[mt][k][0] = f2tf32(r0[8 * k + t]);
                qa[mt][k][1] = f2tf32(r1[8 * k + t]);
                qa[mt][k][2] = f2tf32(r0[8 * k + t + 4]);
                qa[mt][k][3] = f2tf32(r1[8 * k + t + 4]);
            }
        }
    }

    const float sink = sinks[hk * GQA + wid];
    float m[2][2], l[2][2];
#pragma unroll
    for (int mt = 0; mt < 2; mt++) { m[mt][0] = sink; m[mt][1] = sink; l[mt][0] = 0.f; l[mt][1] = 0.f; }

    float o[2][8][4];
#pragma unroll
    for (int mt = 0; mt < 2; mt++)
#pragma unroll
        for (int nt = 0; nt < 8; nt++)
#pragma unroll
            for (int i = 0; i < 4; i++) o[mt][nt][i] = 0.0f;

    const int ldrow = tid >> 4;
    const int ldc4  = tid & 15;

    for (int ch = 0; ch < nch; ch++) {
        const int kb = kbase + ch * KC;
        __syncthreads();
        {
            const size_t rowbase = ((size_t)(b * SEQ + kb + ldrow)) * QKV_N;
            const size_t rowbase2 = rowbase + (size_t)16 * QKV_N;
            float4 kv0 = *(const float4*)(qkv + rowbase + K_OFF + hk * 64 + ldc4 * 4);
            float4 kv1 = *(const float4*)(qkv + rowbase2 + K_OFF + hk * 64 + ldc4 * 4);
            float4 vv0 = *(const float4*)(qkv + rowbase + V_OFF + hk * 64 + ldc4 * 4);
            float4 vv1 = *(const float4*)(qkv + rowbase2 + V_OFF + hk * 64 + ldc4 * 4);
            unsigned* pk0 = &Ks[ldrow * KPAD + ldc4 * 4];
            unsigned* pk1 = &Ks[(ldrow + 16) * KPAD + ldc4 * 4];
            unsigned* pv0 = &Vs[ldrow * KPAD + ldc4 * 4];
            unsigned* pv1 = &Vs[(ldrow + 16) * KPAD + ldc4 * 4];
            pk0[0] = f2tf32(kv0.x); pk0[1] = f2tf32(kv0.y); pk0[2] = f2tf32(kv0.z); pk0[3] = f2tf32(kv0.w);
            pk1[0] = f2tf32(kv1.x); pk1[1] = f2tf32(kv1.y); pk1[2] = f2tf32(kv1.z); pk1[3] = f2tf32(kv1.w);
            pv0[0] = f2tf32(vv0.x); pv0[1] = f2tf32(vv0.y); pv0[2] = f2tf32(vv0.z); pv0[3] = f2tf32(vv0.w);
            pv1[0] = f2tf32(vv1.x); pv1[1] = f2tf32(vv1.y); pv1[2] = f2tf32(vv1.z); pv1[3] = f2tf32(vv1.w);
        }
        __syncthreads();

        float sc[2][4][4];
#pragma unroll
        for (int mt = 0; mt < 2; mt++)
#pragma unroll
            for (int nt = 0; nt < 4; nt++)
#pragma unroll
                for (int i = 0; i < 4; i++) sc[mt][nt][i] = 0.0f;

#pragma unroll
        for (int k = 0; k < 8; k++) {
            unsigned bfr[4][2];
#pragma unroll
            for (int nt = 0; nt < 4; nt++) {
                bfr[nt][0] = Ks[(nt * 8 + g) * KPAD + 8 * k + t];
                bfr[nt][1] = Ks[(nt * 8 + g) * KPAD + 8 * k + t + 4];
            }
#pragma unroll
            for (int mt = 0; mt < 2; mt++)
#pragma unroll
                for (int nt = 0; nt < 4; nt++)
                    mma_tf32(sc[mt][nt], qa[mt][k], bfr[nt]);
        }

#pragma unroll
        for (int mt = 0; mt < 2; mt++) {
            const int qr0 = q0 + mt * 16 + g;
            const int qr1 = qr0 + 8;
            float mx0 = -1e30f, mx1 = -1e30f;
#pragma unroll
            for (int nt = 0; nt < 4; nt++) {
                const int k0c = kb + nt * 8 + 2 * t;
                const int k1c = k0c + 1;
                float s0 = sc[mt][nt][0] * 0.125f;
                float s1 = sc[mt][nt][1] * 0.125f;
                float s2 = sc[mt][nt][2] * 0.125f;
                float s3 = sc[mt][nt][3] * 0.125f;
                s0 = (k0c <= qr0 && qr0 - k0c < WIN) ? s0 : -1e30f;
                s1 = (k1c <= qr0 && qr0 - k1c < WIN) ? s1 : -1e30f;
                s2 = (k0c <= qr1 && qr1 - k0c < WIN) ? s2 : -1e30f;
                s3 = (k1c <= qr1 && qr1 - k1c < WIN) ? s3 : -1e30f;
                sc[mt][nt][0] = s0; sc[mt][nt][1] = s1;
                sc[mt][nt][2] = s2; sc[mt][nt][3] = s3;
                mx0 = fmaxf(mx0, fmaxf(s0, s1));
                mx1 = fmaxf(mx1, fmaxf(s2, s3));
            }
            mx0 = fmaxf(mx0, __shfl_xor_sync(0xFFFFFFFFu, mx0, 1));
            mx0 = fmaxf(mx0, __shfl_xor_sync(0xFFFFFFFFu, mx0, 2));
            mx1 = fmaxf(mx1, __shfl_xor_sync(0xFFFFFFFFu, mx1, 1));
            mx1 = fmaxf(mx1, __shfl_xor_sync(0xFFFFFFFFu, mx1, 2));

            const float mn0 = fmaxf(m[mt][0], mx0);
            const float mn1 = fmaxf(m[mt][1], mx1);
            const float r0 = __expf(m[mt][0] - mn0);
            const float r1 = __expf(m[mt][1] - mn1);
            m[mt][0] = mn0; m[mt][1] = mn1;
            l[mt][0] *= r0; l[mt][1] *= r1;
#pragma unroll
            for (int nt = 0; nt < 8; nt++) {
                o[mt][nt][0] *= r0; o[mt][nt][1] *= r0;
                o[mt][nt][2] *= r1; o[mt][nt][3] *= r1;
            }
            unsigned* prow0 = &Ps[(wid * 32 + mt * 16 + g) * PPAD + 2 * t];
            unsigned* prow1 = prow0 + 8 * PPAD;
#pragma unroll
            for (int nt = 0; nt < 4; nt++) {
                float p0 = __expf(sc[mt][nt][0] - mn0);
                float p1 = __expf(sc[mt][nt][1] - mn0);
                float p2 = __expf(sc[mt][nt][2] - mn1);
                float p3 = __expf(sc[mt][nt][3] - mn1);
                l[mt][0] += p0 + p1;
                l[mt][1] += p2 + p3;
                prow0[nt * 8 + 0] = f2tf32(p0);
                prow0[nt * 8 + 1] = f2tf32(p1);
                prow1[nt * 8 + 0] = f2tf32(p2);
                prow1[nt * 8 + 1] = f2tf32(p3);
            }
        }
        __syncwarp();

#pragma unroll
        for (int kc = 0; kc < 4; kc++) {
            unsigned pa[2][4];
#pragma unroll
            for (int mt = 0; mt < 2; mt++) {
                const unsigned* pr = &Ps[(wid * 32 + mt * 16) * PPAD];
                pa[mt][0] = pr[(g) * PPAD + 8 * kc + t];
                pa[mt][1] = pr[(g + 8) * PPAD + 8 * kc + t];
                pa[mt][2] = pr[(g) * PPAD + 8 * kc + t + 4];
                pa[mt][3] = pr[(g + 8) * PPAD + 8 * kc + t + 4];
            }
#pragma unroll
            for (int nt = 0; nt < 8; nt++) {
                unsigned bv[2];
                bv[0] = Vs[(8 * kc + t) * KPAD + nt * 8 + g];
                bv[1] = Vs[(8 * kc + t + 4) * KPAD + nt * 8 + g];
#pragma unroll
                for (int mt = 0; mt < 2; mt++)
                    mma_tf32(o[mt][nt], pa[mt], bv);
            }
        }
    }

#pragma unroll
    for (int mt = 0; mt < 2; mt++) {
        float l0 = l[mt][0], l1 = l[mt][1];
        l0 += __shfl_xor_sync(0xFFFFFFFFu, l0, 1);
        l0 += __shfl_xor_sync(0xFFFFFFFFu, l0, 2);
        l1 += __shfl_xor_sync(0xFFFFFFFFu, l1, 1);
        l1 += __shfl_xor_sync(0xFFFFFFFFu, l1, 2);
        const float inv0 = 1.0f / (l0 + __expf(sink - m[mt][0]));
        const float inv1 = 1.0f / (l1 + __expf(sink - m[mt][1]));

        const int qr0 = q0 + mt * 16 + g;
        __half* orow0 = out + ((size_t)(b * SEQ + qr0)) * (NH * HD) + (hk * GQA + wid) * HD;
        __half* orow1 = orow0 + (size_t)8 * (NH * HD);
#pragma unroll
        for (int nt = 0; nt < 8; nt++) {
            *(unsigned*)(orow0 + nt * 8 + 2 * t) = pack_h2(o[mt][nt][0] * inv0, o[mt][nt][1] * inv0);
            *(unsigned*)(orow1 + nt * 8 + 2 * t) = pack_h2(o[mt][nt][2] * inv1, o[mt][nt][3] * inv1);
        }
    }
}

// ---------------------------------------------------------------------------
// kernel_launch
// ---------------------------------------------------------------------------
extern "C" void kernel_launch(void* const* d_in, const int* in_sizes, int n_in,
                              void* d_out, int out_size)
{
    const float* x    = (const float*)d_in[0];
    const float* Wq   = (const float*)d_in[1];
    const float* bq   = (const float*)d_in[2];
    const float* Wk   = (const float*)d_in[3];
    const float* bk   = (const float*)d_in[4];
    const float* Wv   = (const float*)d_in[5];
    const float* bv   = (const float*)d_in[6];
    const float* Wo   = (const float*)d_in[7];
    const float* bo   = (const float*)d_in[8];
    const float* sinks = (const float*)d_in[9];
    float* out = (float*)d_out;

    float* qkv = nullptr;
    __half* attnh = nullptr;
    cudaGetSymbolAddress((void**)&qkv, g_qkv);
    cudaGetSymbolAddress((void**)&attnh, g_attnh);

    static bool attr_set = false;
    if (!attr_set) {
        cudaFuncSetAttribute(attn_mma_kernel,
                             cudaFuncAttributeMaxDynamicSharedMemorySize, ATTN_SMEM);
        attr_set = true;
    }

    const int M = BATCH * SEQ;   // 2048

    // fp32 -> fp16 conversion of x and all weights
    cvt_kernel<<<CVT_TOTAL4 / 256, 256>>>(x, Wq, Wk, Wv, Wo);

    // Merged QKV projection (fp16 tensor cores, cp.async + ldmatrix)
    {
        dim3 grid(40, M / 128);
        gemm_qkv<<<grid, 256>>>(bq, bk, bv, qkv);
    }

    // Attention (flash-style, tf32 tensor cores) -> fp16 output
    {
        dim3 grid(SEQ / 32, NHK, BATCH);
        attn_mma_kernel<<<grid, 256, ATTN_SMEM>>>(qkv, sinks, attnh);
    }

    // Output projection (fp16 tensor cores)
    {
        dim3 grid(DM / 128, M / 128);
        gemm_out<<<grid, 256>>>(bo, out);
    }
}

// round 9
// speedup vs baseline: 1.0480x; 1.0480x over previous
#include <cuda_runtime.h>
#include <cuda_fp16.h>
#include <math.h>
#include <stdint.h>

// Problem constants
#define BATCH 2
#define SEQ   1024
#define DM    1024
#define NH    64
#define NHK   8
#define HD    64
#define WIN   128
#define GQA   8
#define QKV_N 5120
#define K_OFF 4096
#define V_OFF 4608

// Scratch (device globals)
__device__ __align__(16) float  g_qkv[BATCH * SEQ * QKV_N];
__device__ __align__(16) __half g_xh[BATCH * SEQ * DM];
__device__ __align__(16) __half g_wqh[NH * HD * DM];
__device__ __align__(16) __half g_wkh[NHK * HD * DM];
__device__ __align__(16) __half g_wvh[NHK * HD * DM];
__device__ __align__(16) __half g_woh[DM * NH * HD];
__device__ __align__(16) __half g_attnh[BATCH * SEQ * NH * HD];

// ---------------------------------------------------------------------------
// helpers
// ---------------------------------------------------------------------------
__device__ __forceinline__ unsigned f2tf32(float x) {
    unsigned u;
    asm("cvt.rna.tf32.f32 %0, %1;" : "=r"(u) : "f"(x));
    return u;
}
__device__ __forceinline__ unsigned pack_h2(float a, float b) {
    __half2 h = __floats2half2_rn(a, b);
    return *(unsigned*)&h;
}
__device__ __forceinline__ uint32_t smem_u32(const void* p) {
    uint32_t a;
    asm("{ .reg .u64 t; cvta.to.shared.u64 t, %1; cvt.u32.u64 %0, t; }" : "=r"(a) : "l"(p));
    return a;
}
#define CP16(dst, src) \
    asm volatile("cp.async.cg.shared.global [%0], [%1], 16;" \
        :: "r"(dst), "l"(__cvta_generic_to_global(src)))
#define CP_COMMIT() asm volatile("cp.async.commit_group;")
#define CP_WAIT(n)  asm volatile("cp.async.wait_group %0;" :: "n"(n))
#define LDSM_X4(r0, r1, r2, r3, addr) \
    asm volatile("ldmatrix.sync.aligned.m8n8.x4.shared.b16 {%0,%1,%2,%3}, [%4];" \
        : "=r"(r0), "=r"(r1), "=r"(r2), "=r"(r3) : "r"(addr))

__device__ __forceinline__ void mma_f16(float* c, const unsigned* a, const unsigned* b) {
    asm volatile(
        "mma.sync.aligned.m16n8k16.row.col.f32.f16.f16.f32 "
        "{%0,%1,%2,%3}, {%4,%5,%6,%7}, {%8,%9}, {%0,%1,%2,%3};"
        : "+f"(c[0]), "+f"(c[1]), "+f"(c[2]), "+f"(c[3])
        : "r"(a[0]), "r"(a[1]), "r"(a[2]), "r"(a[3]), "r"(b[0]), "r"(b[1]));
}
__device__ __forceinline__ void mma_tf32(float* c, const unsigned* a, const unsigned* b) {
    asm volatile(
        "mma.sync.aligned.m16n8k8.row.col.f32.tf32.tf32.f32 "
        "{%0,%1,%2,%3}, {%4,%5,%6,%7}, {%8,%9}, {%0,%1,%2,%3};"
        : "+f"(c[0]), "+f"(c[1]), "+f"(c[2]), "+f"(c[3])
        : "r"(a[0]), "r"(a[1]), "r"(a[2]), "r"(a[3]), "r"(b[0]), "r"(b[1]));
}

// ---------------------------------------------------------------------------
// fp32 -> fp16 conversion of x + all weights (one kernel)
// ---------------------------------------------------------------------------
#define CVT_TOTAL4 2883584
__global__ __launch_bounds__(256) void cvt_kernel(
    const float* __restrict__ x,  const float* __restrict__ wq,
    const float* __restrict__ wk, const float* __restrict__ wv,
    const float* __restrict__ wo)
{
    size_t i = (size_t)blockIdx.x * 256 + threadIdx.x;
    const float* src; __half* dst; size_t off;
    if (i < 524288)       { src = x;  dst = g_xh;  off = i; }
    else if (i < 1572864) { src = wq; dst = g_wqh; off = i - 524288; }
    else if (i < 1703936) { src = wk; dst = g_wkh; off = i - 1572864; }
    else if (i < 1835008) { src = wv; dst = g_wvh; off = i - 1703936; }
    else                  { src = wo; dst = g_woh; off = i - 1835008; }
    float4 v = ((const float4*)src)[off];
    ((uint2*)dst)[off] = make_uint2(pack_h2(v.x, v.y), pack_h2(v.z, v.w));
}

// ---------------------------------------------------------------------------
// FP16 GEMM core: 512 threads / 16 warps, warp tile 16(M) x 64(N).
// C[128,128] tile = A[M,K](half) @ B[128,K](half)^T + bias(f32), C f32.
// cp.async 3-stage pipeline; smem rows 32 halves (4x16B chunks),
// chunk swizzle c ^ ((r>>1)&3); ldmatrix.x4 fragment loads.
// ---------------------------------------------------------------------------
__device__ __forceinline__ void gemm_h_core(
    const __half* __restrict__ A, const __half* __restrict__ Bw,
    const float* __restrict__ bias, float* __restrict__ Cg,
    int K, int ldc, int by, int colbase)
{
    __shared__ uint32_t S[12288];   // 48KB: A[3][2048] + B[3][2048]

    const int tid  = threadIdx.x;
    const int wid  = tid >> 5;
    const int lane = tid & 31;
    const int wm   = wid & 7;      // 8 row groups of 16
    const int wn   = wid >> 3;     // 2 col groups of 64
    const int g    = lane >> 2;
    const int t    = lane & 3;

    const __half* Ag = A + (size_t)(by * 128) * K;

    // cp.async store geometry: 512 threads -> 1 chunk per matrix per stage
    const int r    = tid >> 2;          // row 0..127
    const int c    = tid & 3;           // chunk 0..3
    const int swst = (r >> 1) & 3;
    const uint32_t sb  = smem_u32(S);
    const uint32_t ad  = sb + r * 64 + (((c ^ swst)) << 4);
    const __half* arow = Ag + (size_t)r * K + c * 8;
    const __half* brow = Bw + (size_t)r * K + c * 8;

    // ldmatrix geometry
    const int lane15 = lane & 15;
    const int hiA  = lane >> 4;
    const int rowA = wm * 16 + lane15;
    const int swA  = (rowA >> 1) & 3;
    const uint32_t offA = (uint32_t)rowA * 64;
    const int hiB  = (lane >> 3) & 1;
    const int rowBb = wn * 64 + ((lane >> 4) & 1) * 8 + (lane & 7);

    float acc[8][4];
#pragma unroll
    for (int nt = 0; nt < 8; nt++)
#pragma unroll
        for (int i = 0; i < 4; i++) acc[nt][i] = 0.0f;

    const int niter = K >> 5;

#pragma unroll
    for (int s = 0; s < 2; s++) {
        const uint32_t bo = s * 8192;
        CP16(ad + bo, arow + s * 32);
        CP16(ad + bo + 24576, brow + s * 32);
        CP_COMMIT();
    }

    for (int it = 0; it < niter; it++) {
        const int buf = it % 3;
        if (it + 1 < niter) { CP_WAIT(1); } else { CP_WAIT(0); }
        __syncthreads();

        // prefetch stage it+2 (its buffer was last read at iter it-1)
        if (it + 2 < niter) {
            const int s = it + 2;
            const uint32_t bo = (s % 3) * 8192;
            CP16(ad + bo, arow + (size_t)s * 32);
            CP16(ad + bo + 24576, brow + (size_t)s * 32);
            CP_COMMIT();
        }

        const uint32_t sa  = sb + buf * 8192;
        const uint32_t sbb = sa + 24576;

#pragma unroll
        for (int kk = 0; kk < 2; kk++) {
            unsigned a[4], b[8][2];
            const int cA = 2 * kk + hiA;
            LDSM_X4(a[0], a[1], a[2], a[3], sa + offA + (((cA ^ swA)) << 4));
            const int cB = 2 * kk + hiB;
#pragma unroll
            for (int p = 0; p < 4; p++) {
                const int rowB = rowBb + p * 16;
                const int swB = (rowB >> 1) & 3;
                LDSM_X4(b[2 * p][0], b[2 * p][1], b[2 * p + 1][0], b[2 * p + 1][1],
                        sbb + (uint32_t)rowB * 64 + (((cB ^ swB)) << 4));
            }
#pragma unroll
            for (int nt = 0; nt < 8; nt++)
                mma_f16(acc[nt], a, b[nt]);
        }
    }

    // epilogue with bias
    {
        const int row0 = by * 128 + wm * 16 + g;
#pragma unroll
        for (int nt = 0; nt < 8; nt++) {
            const int col = wn * 64 + nt * 8 + 2 * t;
            const float b0 = bias[col], b1 = bias[col + 1];
            float2 o0 = make_float2(acc[nt][0] + b0, acc[nt][1] + b1);
            float2 o1 = make_float2(acc[nt][2] + b0, acc[nt][3] + b1);
            *(float2*)(Cg + (size_t)row0 * ldc + colbase + col) = o0;
            *(float2*)(Cg + (size_t)(row0 + 8) * ldc + colbase + col) = o1;
        }
    }
}

// Merged QKV projection: grid.x in [0,40): 0-31 Q, 32-35 K, 36-39 V
__global__ __launch_bounds__(512, 1) void gemm_qkv(
    const float* __restrict__ bq, const float* __restrict__ bk,
    const float* __restrict__ bv, float* __restrict__ C)
{
    const int bx = blockIdx.x;
    const __half* W; const float* bias; int wt, seg;
    if (bx < 32)      { W = g_wqh; bias = bq; wt = bx;      seg = 0; }
    else if (bx < 36) { W = g_wkh; bias = bk; wt = bx - 32; seg = K_OFF; }
    else              { W = g_wvh; bias = bv; wt = bx - 36; seg = V_OFF; }
    gemm_h_core(g_xh, W + (size_t)wt * 128 * DM, bias + wt * 128,
                C, DM, QKV_N, blockIdx.y, seg + wt * 128);
}

// Output projection
__global__ __launch_bounds__(512, 1) void gemm_out(
    const float* __restrict__ bias, float* __restrict__ C)
{
    gemm_h_core(g_attnh, g_woh + (size_t)blockIdx.x * 128 * (NH * HD),
                bias + blockIdx.x * 128, C, NH * HD, DM, blockIdx.y, blockIdx.x * 128);
}

// ---------------------------------------------------------------------------
// Flash-style sliding-window GQA attention with sink logit (unchanged R7)
// ---------------------------------------------------------------------------
#define KC   32
#define KPAD 68
#define PPAD 36
#define KS_OFF 0
#define VS_OFF (KC * KPAD)
#define PS_OFF (2 * KC * KPAD)
#define ATTN_SMEM ((2 * KC * KPAD + 256 * PPAD) * 4)

__global__ __launch_bounds__(256) void attn_mma_kernel(
    const float* __restrict__ qkv, const float* __restrict__ sinks,
    __half* __restrict__ out)
{
    extern __shared__ unsigned asmem[];
    unsigned* Ks = asmem + KS_OFF;
    unsigned* Vs = asmem + VS_OFF;
    unsigned* Ps = asmem + PS_OFF;

    const int q0  = blockIdx.x * 32;
    const int hk  = blockIdx.y;
    const int b   = blockIdx.z;
    const int tid = threadIdx.x;
    const int wid = tid >> 5;
    const int lane = tid & 31;
    const int g = lane >> 2;
    const int t = lane & 3;

    const int kbase = (q0 >= 128) ? (q0 - 128) : 0;
    const int nch = (q0 + 32 - kbase) >> 5;

    unsigned qa[2][8][4];
    {
        const float* qrow = qkv + ((size_t)(b * SEQ + q0)) * QKV_N + hk * 512 + wid * 64;
#pragma unroll
        for (int mt = 0; mt < 2; mt++) {
            const float* r0 = qrow + (size_t)(mt * 16 + g) * QKV_N;
            const float* r1 = r0 + (size_t)8 * QKV_N;
#pragma unroll
            for (int k = 0; k < 8; k++) {
                qa[mt][k][0] = f2tf32(r0[8 * k + t]);
                qa[mt][k][1] = f2tf32(r1[8 * k + t]);
                qa[mt][k][2] = f2tf32(r0[8 * k + t + 4]);
                qa[mt][k][3] = f2tf32(r1[8 * k + t + 4]);
            }
        }
    }

    const float sink = sinks[hk * GQA + wid];
    float m[2][2], l[2][2];
#pragma unroll
    for (int mt = 0; mt < 2; mt++) { m[mt][0] = sink; m[mt][1] = sink; l[mt][0] = 0.f; l[mt][1] = 0.f; }

    float o[2][8][4];
#pragma unroll
    for (int mt = 0; mt < 2; mt++)
#pragma unroll
        for (int nt = 0; nt < 8; nt++)
#pragma unroll
            for (int i = 0; i < 4; i++) o[mt][nt][i] = 0.0f;

    const int ldrow = tid >> 4;
    const int ldc4  = tid & 15;

    for (int ch = 0; ch < nch; ch++) {
        const int kb = kbase + ch * KC;
        __syncthreads();
        {
            const size_t rowbase = ((size_t)(b * SEQ + kb + ldrow)) * QKV_N;
            const size_t rowbase2 = rowbase + (size_t)16 * QKV_N;
            float4 kv0 = *(const float4*)(qkv + rowbase + K_OFF + hk * 64 + ldc4 * 4);
            float4 kv1 = *(const float4*)(qkv + rowbase2 + K_OFF + hk * 64 + ldc4 * 4);
            float4 vv0 = *(const float4*)(qkv + rowbase + V_OFF + hk * 64 + ldc4 * 4);
            float4 vv1 = *(const float4*)(qkv + rowbase2 + V_OFF + hk * 64 + ldc4 * 4);
            unsigned* pk0 = &Ks[ldrow * KPAD + ldc4 * 4];
            unsigned* pk1 = &Ks[(ldrow + 16) * KPAD + ldc4 * 4];
            unsigned* pv0 = &Vs[ldrow * KPAD + ldc4 * 4];
            unsigned* pv1 = &Vs[(ldrow + 16) * KPAD + ldc4 * 4];
            pk0[0] = f2tf32(kv0.x); pk0[1] = f2tf32(kv0.y); pk0[2] = f2tf32(kv0.z); pk0[3] = f2tf32(kv0.w);
            pk1[0] = f2tf32(kv1.x); pk1[1] = f2tf32(kv1.y); pk1[2] = f2tf32(kv1.z); pk1[3] = f2tf32(kv1.w);
            pv0[0] = f2tf32(vv0.x); pv0[1] = f2tf32(vv0.y); pv0[2] = f2tf32(vv0.z); pv0[3] = f2tf32(vv0.w);
            pv1[0] = f2tf32(vv1.x); pv1[1] = f2tf32(vv1.y); pv1[2] = f2tf32(vv1.z); pv1[3] = f2tf32(vv1.w);
        }
        __syncthreads();

        float sc[2][4][4];
#pragma unroll
        for (int mt = 0; mt < 2; mt++)
#pragma unroll
            for (int nt = 0; nt < 4; nt++)
#pragma unroll
                for (int i = 0; i < 4; i++) sc[mt][nt][i] = 0.0f;

#pragma unroll
        for (int k = 0; k < 8; k++) {
            unsigned bfr[4][2];
#pragma unroll
            for (int nt = 0; nt < 4; nt++) {
                bfr[nt][0] = Ks[(nt * 8 + g) * KPAD + 8 * k + t];
                bfr[nt][1] = Ks[(nt * 8 + g) * KPAD + 8 * k + t + 4];
            }
#pragma unroll
            for (int mt = 0; mt < 2; mt++)
#pragma unroll
                for (int nt = 0; nt < 4; nt++)
                    mma_tf32(sc[mt][nt], qa[mt][k], bfr[nt]);
        }

#pragma unroll
        for (int mt = 0; mt < 2; mt++) {
            const int qr0 = q0 + mt * 16 + g;
            const int qr1 = qr0 + 8;
            float mx0 = -1e30f, mx1 = -1e30f;
#pragma unroll
            for (int nt = 0; nt < 4; nt++) {
                const int k0c = kb + nt * 8 + 2 * t;
                const int k1c = k0c + 1;
                float s0 = sc[mt][nt][0] * 0.125f;
                float s1 = sc[mt][nt][1] * 0.125f;
                float s2 = sc[mt][nt][2] * 0.125f;
                float s3 = sc[mt][nt][3] * 0.125f;
                s0 = (k0c <= qr0 && qr0 - k0c < WIN) ? s0 : -1e30f;
                s1 = (k1c <= qr0 && qr0 - k1c < WIN) ? s1 : -1e30f;
                s2 = (k0c <= qr1 && qr1 - k0c < WIN) ? s2 : -1e30f;
                s3 = (k1c <= qr1 && qr1 - k1c < WIN) ? s3 : -1e30f;
                sc[mt][nt][0] = s0; sc[mt][nt][1] = s1;
                sc[mt][nt][2] = s2; sc[mt][nt][3] = s3;
                mx0 = fmaxf(mx0, fmaxf(s0, s1));
                mx1 = fmaxf(mx1, fmaxf(s2, s3));
            }
            mx0 = fmaxf(mx0, __shfl_xor_sync(0xFFFFFFFFu, mx0, 1));
            mx0 = fmaxf(mx0, __shfl_xor_sync(0xFFFFFFFFu, mx0, 2));
            mx1 = fmaxf(mx1, __shfl_xor_sync(0xFFFFFFFFu, mx1, 1));
            mx1 = fmaxf(mx1, __shfl_xor_sync(0xFFFFFFFFu, mx1, 2));

            const float mn0 = fmaxf(m[mt][0], mx0);
            const float mn1 = fmaxf(m[mt][1], mx1);
            const float r0 = __expf(m[mt][0] - mn0);
            const float r1 = __expf(m[mt][1] - mn1);
            m[mt][0] = mn0; m[mt][1] = mn1;
            l[mt][0] *= r0; l[mt][1] *= r1;
#pragma unroll
            for (int nt = 0; nt < 8; nt++) {
                o[mt][nt][0] *= r0; o[mt][nt][1] *= r0;
                o[mt][nt][2] *= r1; o[mt][nt][3] *= r1;
            }
            unsigned* prow0 = &Ps[(wid * 32 + mt * 16 + g) * PPAD + 2 * t];
            unsigned* prow1 = prow0 + 8 * PPAD;
#pragma unroll
            for (int nt = 0; nt < 4; nt++) {
                float p0 = __expf(sc[mt][nt][0] - mn0);
                float p1 = __expf(sc[mt][nt][1] - mn0);
                float p2 = __expf(sc[mt][nt][2] - mn1);
                float p3 = __expf(sc[mt][nt][3] - mn1);
                l[mt][0] += p0 + p1;
                l[mt][1] += p2 + p3;
                prow0[nt * 8 + 0] = f2tf32(p0);
                prow0[nt * 8 + 1] = f2tf32(p1);
                prow1[nt * 8 + 0] = f2tf32(p2);
                prow1[nt * 8 + 1] = f2tf32(p3);
            }
        }
        __syncwarp();

#pragma unroll
        for (int kc = 0; kc < 4; kc++) {
            unsigned pa[2][4];
#pragma unroll
            for (int mt = 0; mt < 2; mt++) {
                const unsigned* pr = &Ps[(wid * 32 + mt * 16) * PPAD];
                pa[mt][0] = pr[(g) * PPAD + 8 * kc + t];
                pa[mt][1] = pr[(g + 8) * PPAD + 8 * kc + t];
                pa[mt][2] = pr[(g) * PPAD + 8 * kc + t + 4];
                pa[mt][3] = pr[(g + 8) * PPAD + 8 * kc + t + 4];
            }
#pragma unroll
            for (int nt = 0; nt < 8; nt++) {
                unsigned bv[2];
                bv[0] = Vs[(8 * kc + t) * KPAD + nt * 8 + g];
                bv[1] = Vs[(8 * kc + t + 4) * KPAD + nt * 8 + g];
#pragma unroll
                for (int mt = 0; mt < 2; mt++)
                    mma_tf32(o[mt][nt], pa[mt], bv);
            }
        }
    }

#pragma unroll
    for (int mt = 0; mt < 2; mt++) {
        float l0 = l[mt][0], l1 = l[mt][1];
        l0 += __shfl_xor_sync(0xFFFFFFFFu, l0, 1);
        l0 += __shfl_xor_sync(0xFFFFFFFFu, l0, 2);
        l1 += __shfl_xor_sync(0xFFFFFFFFu, l1, 1);
        l1 += __shfl_xor_sync(0xFFFFFFFFu, l1, 2);
        const float inv0 = 1.0f / (l0 + __expf(sink - m[mt][0]));
        const float inv1 = 1.0f / (l1 + __expf(sink - m[mt][1]));

        const int qr0 = q0 + mt * 16 + g;
        __half* orow0 = out + ((size_t)(b * SEQ + qr0)) * (NH * HD) + (hk * GQA + wid) * HD;
        __half* orow1 = orow0 + (size_t)8 * (NH * HD);
#pragma unroll
        for (int nt = 0; nt < 8; nt++) {
            *(unsigned*)(orow0 + nt * 8 + 2 * t) = pack_h2(o[mt][nt][0] * inv0, o[mt][nt][1] * inv0);
            *(unsigned*)(orow1 + nt * 8 + 2 * t) = pack_h2(o[mt][nt][2] * inv1, o[mt][nt][3] * inv1);
        }
    }
}

// ---------------------------------------------------------------------------
// kernel_launch
// ---------------------------------------------------------------------------
extern "C" void kernel_launch(void* const* d_in, const int* in_sizes, int n_in,
                              void* d_out, int out_size)
{
    const float* x    = (const float*)d_in[0];
    const float* Wq   = (const float*)d_in[1];
    const float* bq   = (const float*)d_in[2];
    const float* Wk   = (const float*)d_in[3];
    const float* bk   = (const float*)d_in[4];
    const float* Wv   = (const float*)d_in[5];
    const float* bv   = (const float*)d_in[6];
    const float* Wo   = (const float*)d_in[7];
    const float* bo   = (const float*)d_in[8];
    const float* sinks = (const float*)d_in[9];
    float* out = (float*)d_out;

    float* qkv = nullptr;
    __half* attnh = nullptr;
    cudaGetSymbolAddress((void**)&qkv, g_qkv);
    cudaGetSymbolAddress((void**)&attnh, g_attnh);

    static bool attr_set = false;
    if (!attr_set) {
        cudaFuncSetAttribute(attn_mma_kernel,
                             cudaFuncAttributeMaxDynamicSharedMemorySize, ATTN_SMEM);
        attr_set = true;
    }

    const int M = BATCH * SEQ;   // 2048

    // fp32 -> fp16 conversion of x and all weights
    cvt_kernel<<<CVT_TOTAL4 / 256, 256>>>(x, Wq, Wk, Wv, Wo);

    // Merged QKV projection (fp16 tensor cores, 512 threads)
    {
        dim3 grid(40, M / 128);
        gemm_qkv<<<grid, 512>>>(bq, bk, bv, qkv);
    }

    // Attention (flash-style, tf32 tensor cores) -> fp16 output
    {
        dim3 grid(SEQ / 32, NHK, BATCH);
        attn_mma_kernel<<<grid, 256, ATTN_SMEM>>>(qkv, sinks, attnh);
    }

    // Output projection (fp16 tensor cores, 512 threads)
    {
        dim3 grid(DM / 128, M / 128);
        gemm_out<<<grid, 512>>>(bo, out);
    }
}

// round 10
// speedup vs baseline: 1.2271x; 1.1710x over previous
#include <cuda_runtime.h>
#include <cuda_fp16.h>
#include <math.h>
#include <stdint.h>

// Problem constants
#define BATCH 2
#define SEQ   1024
#define DM    1024
#define NH    64
#define NHK   8
#define HD    64
#define WIN   128
#define GQA   8
#define QKV_N 5120
#define K_OFF 4096
#define V_OFF 4608
#define KC    32

// Scratch (device globals)
__device__ __align__(16) __half g_qkvh[BATCH * SEQ * QKV_N];   // fp16 QKV (bias added)
__device__ __align__(16) __half g_xh[BATCH * SEQ * DM];
__device__ __align__(16) __half g_wqh[NH * HD * DM];
__device__ __align__(16) __half g_wkh[NHK * HD * DM];
__device__ __align__(16) __half g_wvh[NHK * HD * DM];
__device__ __align__(16) __half g_woh[DM * NH * HD];
__device__ __align__(16) __half g_attnh[BATCH * SEQ * NH * HD];

// ---------------------------------------------------------------------------
// helpers
// ---------------------------------------------------------------------------
__device__ __forceinline__ unsigned pack_h2(float a, float b) {
    __half2 h = __floats2half2_rn(a, b);
    return *(unsigned*)&h;
}
__device__ __forceinline__ uint32_t smem_u32(const void* p) {
    uint32_t a;
    asm("{ .reg .u64 t; cvta.to.shared.u64 t, %1; cvt.u32.u64 %0, t; }" : "=r"(a) : "l"(p));
    return a;
}
#define CP16(dst, src) \
    asm volatile("cp.async.cg.shared.global [%0], [%1], 16;" \
        :: "r"(dst), "l"(__cvta_generic_to_global(src)))
#define CP_COMMIT() asm volatile("cp.async.commit_group;")
#define CP_WAIT(n)  asm volatile("cp.async.wait_group %0;" :: "n"(n))
#define LDSM_X4(r0, r1, r2, r3, addr) \
    asm volatile("ldmatrix.sync.aligned.m8n8.x4.shared.b16 {%0,%1,%2,%3}, [%4];" \
        : "=r"(r0), "=r"(r1), "=r"(r2), "=r"(r3) : "r"(addr))
#define LDSM_X2T(r0, r1, addr) \
    asm volatile("ldmatrix.sync.aligned.m8n8.x2.trans.shared.b16 {%0,%1}, [%2];" \
        : "=r"(r0), "=r"(r1) : "r"(addr))

__device__ __forceinline__ void mma_f16(float* c, const unsigned* a, const unsigned* b) {
    asm volatile(
        "mma.sync.aligned.m16n8k16.row.col.f32.f16.f16.f32 "
        "{%0,%1,%2,%3}, {%4,%5,%6,%7}, {%8,%9}, {%0,%1,%2,%3};"
        : "+f"(c[0]), "+f"(c[1]), "+f"(c[2]), "+f"(c[3])
        : "r"(a[0]), "r"(a[1]), "r"(a[2]), "r"(a[3]), "r"(b[0]), "r"(b[1]));
}

// ---------------------------------------------------------------------------
// fp32 -> fp16 conversion of x + all weights
// ---------------------------------------------------------------------------
#define CVT_TOTAL4 2883584
__global__ __launch_bounds__(256) void cvt_kernel(
    const float* __restrict__ x,  const float* __restrict__ wq,
    const float* __restrict__ wk, const float* __restrict__ wv,
    const float* __restrict__ wo)
{
    size_t i = (size_t)blockIdx.x * 256 + threadIdx.x;
    const float* src; __half* dst; size_t off;
    if (i < 524288)       { src = x;  dst = g_xh;  off = i; }
    else if (i < 1572864) { src = wq; dst = g_wqh; off = i - 524288; }
    else if (i < 1703936) { src = wk; dst = g_wkh; off = i - 1572864; }
    else if (i < 1835008) { src = wv; dst = g_wvh; off = i - 1703936; }
    else                  { src = wo; dst = g_woh; off = i - 1835008; }
    float4 v = ((const float4*)src)[off];
    ((uint2*)dst)[off] = make_uint2(pack_h2(v.x, v.y), pack_h2(v.z, v.w));
}

// ---------------------------------------------------------------------------
// FP16 GEMM core, BK=64: C[128,128] tile = A[M,K] @ B[128,K]^T + bias.
// 512 threads / 16 warps, warp tile 16(M) x 64(N).
// 3-stage cp.async pipeline, dynamic smem 96KB.
// Smem rows: 64 halves = 128B = 8 chunks of 16B, swizzle c ^ (r&7).
// ---------------------------------------------------------------------------
#define GEMM_SMEM 98304
#define STAGE_B   16384
#define BOFF      49152

template <bool HOUT>
__device__ __forceinline__ void gemm_h_core(
    const __half* __restrict__ A, const __half* __restrict__ Bw,
    const float* __restrict__ bias, float* __restrict__ Cf, __half* __restrict__ Ch,
    int K, int ldc, int by, int colbase)
{
    extern __shared__ uint32_t Sg[];

    const int tid  = threadIdx.x;
    const int wid  = tid >> 5;
    const int lane = tid & 31;
    const int wm   = wid & 7;
    const int wn   = wid >> 3;
    const int g    = lane >> 2;
    const int t    = lane & 3;

    const __half* Ag = A + (size_t)(by * 128) * K;
    const uint32_t sb = smem_u32(Sg);

    // cp.async store geometry: row r, chunks c0, c0+1
    const int r  = tid >> 2;
    const int c0 = (tid & 3) * 2;
    const int rsw = r & 7;
    const uint32_t adA0 = sb + r * 128 + (((c0 + 0) ^ rsw) << 4);
    const uint32_t adA1 = sb + r * 128 + (((c0 + 1) ^ rsw) << 4);
    const __half* arow = Ag + (size_t)r * K + c0 * 8;
    const __half* brow = Bw + (size_t)r * K + c0 * 8;

    // ldmatrix geometry
    const int lane15 = lane & 15;
    const int hiA  = lane >> 4;
    const int rowA = wm * 16 + lane15;
    const uint32_t offA = (uint32_t)rowA * 128;
    const int swA = rowA & 7;
    const int hiB = (lane >> 3) & 1;
    const int rowBb = wn * 64 + ((lane >> 4) & 1) * 8 + (lane & 7);

    float acc[8][4];
#pragma unroll
    for (int nt = 0; nt < 8; nt++)
#pragma unroll
        for (int i = 0; i < 4; i++) acc[nt][i] = 0.0f;

    const int niter = K >> 6;

#pragma unroll
    for (int s = 0; s < 2; s++) {
        const uint32_t bo = s * STAGE_B;
        CP16(adA0 + bo, arow + s * 64);
        CP16(adA1 + bo, arow + s * 64 + 8);
        CP16(adA0 + bo + BOFF, brow + s * 64);
        CP16(adA1 + bo + BOFF, brow + s * 64 + 8);
        CP_COMMIT();
    }

    for (int it = 0; it < niter; it++) {
        const int buf = it % 3;
        if (it + 1 < niter) { CP_WAIT(1); } else { CP_WAIT(0); }
        __syncthreads();

        if (it + 2 < niter) {
            const int s = it + 2;
            const uint32_t bo = (s % 3) * STAGE_B;
            CP16(adA0 + bo, arow + (size_t)s * 64);
            CP16(adA1 + bo, arow + (size_t)s * 64 + 8);
            CP16(adA0 + bo + BOFF, brow + (size_t)s * 64);
            CP16(adA1 + bo + BOFF, brow + (size_t)s * 64 + 8);
            CP_COMMIT();
        }

        const uint32_t sa  = sb + buf * STAGE_B;
        const uint32_t sbb = sa + BOFF;

#pragma unroll
        for (int ks = 0; ks < 4; ks++) {
            unsigned a[4], b[8][2];
            const int cA = 2 * ks + hiA;
            LDSM_X4(a[0], a[1], a[2], a[3], sa + offA + (((cA ^ swA)) << 4));
            const int cB = 2 * ks + hiB;
#pragma unroll
            for (int p = 0; p < 4; p++) {
                const int rowB = rowBb + p * 16;
                LDSM_X4(b[2 * p][0], b[2 * p][1], b[2 * p + 1][0], b[2 * p + 1][1],
                        sbb + (uint32_t)rowB * 128 + (((cB ^ (rowB & 7))) << 4));
            }
#pragma unroll
            for (int nt = 0; nt < 8; nt++)
                mma_f16(acc[nt], a, b[nt]);
        }
    }

    // epilogue with bias
    {
        const int row0 = by * 128 + wm * 16 + g;
#pragma unroll
        for (int nt = 0; nt < 8; nt++) {
            const int col = wn * 64 + nt * 8 + 2 * t;
            const float b0 = bias[col], b1 = bias[col + 1];
            if (HOUT) {
                *(unsigned*)(Ch + (size_t)row0 * ldc + colbase + col) =
                    pack_h2(acc[nt][0] + b0, acc[nt][1] + b1);
                *(unsigned*)(Ch + (size_t)(row0 + 8) * ldc + colbase + col) =
                    pack_h2(acc[nt][2] + b0, acc[nt][3] + b1);
            } else {
                float2 o0 = make_float2(acc[nt][0] + b0, acc[nt][1] + b1);
                float2 o1 = make_float2(acc[nt][2] + b0, acc[nt][3] + b1);
                *(float2*)(Cf + (size_t)row0 * ldc + colbase + col) = o0;
                *(float2*)(Cf + (size_t)(row0 + 8) * ldc + colbase + col) = o1;
            }
        }
    }
}

// Merged QKV projection -> fp16 qkv buffer
__global__ __launch_bounds__(512, 1) void gemm_qkv(
    const float* __restrict__ bq, const float* __restrict__ bk,
    const float* __restrict__ bv)
{
    const int bx = blockIdx.x;
    const __half* W; const float* bias; int wt, seg;
    if (bx < 32)      { W = g_wqh; bias = bq; wt = bx;      seg = 0; }
    else if (bx < 36) { W = g_wkh; bias = bk; wt = bx - 32; seg = K_OFF; }
    else              { W = g_wvh; bias = bv; wt = bx - 36; seg = V_OFF; }
    gemm_h_core<true>(g_xh, W + (size_t)wt * 128 * DM, bias + wt * 128,
                      nullptr, g_qkvh, DM, QKV_N, blockIdx.y, seg + wt * 128);
}

// Output projection (f32 out)
__global__ __launch_bounds__(512, 1) void gemm_out(
    const float* __restrict__ bias, float* __restrict__ C)
{
    gemm_h_core<false>(g_attnh, g_woh + (size_t)blockIdx.x * 128 * (NH * HD),
                       bias + blockIdx.x * 128, C, nullptr,
                       NH * HD, DM, blockIdx.y, blockIdx.x * 128);
}

// ---------------------------------------------------------------------------
// Fully-fp16 flash attention: CTA = (32 queries, kv-head, batch), 256 threads,
// warp = head. Q frags from global; K/V via double-buffered cp.async;
// P packed directly from accumulator fragments (no smem round-trip).
// ---------------------------------------------------------------------------
__global__ __launch_bounds__(256) void attn_h_kernel(
    const __half* __restrict__ qkv, const float* __restrict__ sinks,
    __half* __restrict__ out)
{
    __shared__ uint32_t KV[4096];   // K: 2 x 4KB, V: 2 x 4KB

    const int q0  = blockIdx.x * 32;
    const int hk  = blockIdx.y;
    const int b   = blockIdx.z;
    const int tid = threadIdx.x;
    const int wid = tid >> 5;
    const int lane = tid & 31;
    const int g = lane >> 2;
    const int t = lane & 3;

    const int kbase = (q0 >= 128) ? (q0 - 128) : 0;
    const int nch = (q0 + 32 - kbase) >> 5;
    const uint32_t kvb = smem_u32(KV);

    // --- Q fragments (fp16) straight from global ---
    unsigned qa[2][4][4];
    {
        const __half* qrow = qkv + ((size_t)(b * SEQ + q0)) * QKV_N + hk * 512 + wid * 64;
#pragma unroll
        for (int mt = 0; mt < 2; mt++) {
            const __half* r0 = qrow + (size_t)(mt * 16 + g) * QKV_N;
            const __half* r1 = r0 + (size_t)8 * QKV_N;
#pragma unroll
            for (int ks = 0; ks < 4; ks++) {
                qa[mt][ks][0] = *(const unsigned*)(r0 + ks * 16 + 2 * t);
                qa[mt][ks][1] = *(const unsigned*)(r1 + ks * 16 + 2 * t);
                qa[mt][ks][2] = *(const unsigned*)(r0 + ks * 16 + 8 + 2 * t);
                qa[mt][ks][3] = *(const unsigned*)(r1 + ks * 16 + 8 + 2 * t);
            }
        }
    }

    const float sink = sinks[hk * GQA + wid];
    float m[2][2], l[2][2];
#pragma unroll
    for (int mt = 0; mt < 2; mt++) { m[mt][0] = sink; m[mt][1] = sink; l[mt][0] = 0.f; l[mt][1] = 0.f; }

    float o[2][8][4];
#pragma unroll
    for (int mt = 0; mt < 2; mt++)
#pragma unroll
        for (int nt = 0; nt < 8; nt++)
#pragma unroll
            for (int i = 0; i < 4; i++) o[mt][nt][i] = 0.0f;

    // loader geometry: 256 threads, 1 chunk/matrix each (32 rows x 8 chunks)
    const int lr = tid >> 3;
    const int lc = tid & 7;
    const uint32_t koff = (uint32_t)lr * 128 + (((lc ^ (lr & 7))) << 4);
    const __half* kg = qkv + K_OFF + hk * 64 + lc * 8;
    const __half* vg = qkv + V_OFF + hk * 64 + lc * 8;

    // prologue: chunk 0 -> buffer 0
    {
        size_t rb = ((size_t)(b * SEQ + kbase + lr)) * QKV_N;
        CP16(kvb + koff, kg + rb);
        CP16(kvb + 8192 + koff, vg + rb);
        CP_COMMIT();
    }

    for (int ch = 0; ch < nch; ch++) {
        const int kb = kbase + ch * KC;
        const uint32_t kbuf = kvb + (ch & 1) * 4096;
        const uint32_t vbuf = kbuf + 8192;

        CP_WAIT(0);
        __syncthreads();

        if (ch + 1 < nch) {
            size_t rb = ((size_t)(b * SEQ + kb + KC + lr)) * QKV_N;
            uint32_t nb = kvb + ((ch + 1) & 1) * 4096;
            CP16(nb + koff, kg + rb);
            CP16(nb + 8192 + koff, vg + rb);
            CP_COMMIT();
        }

        // ---- QK^T: 32q x 32k, fp16 k16 x4 ----
        float sc[2][4][4];
#pragma unroll
        for (int mt = 0; mt < 2; mt++)
#pragma unroll
            for (int nt = 0; nt < 4; nt++)
#pragma unroll
                for (int i = 0; i < 4; i++) sc[mt][nt][i] = 0.0f;

#pragma unroll
        for (int ks = 0; ks < 4; ks++) {
            unsigned bf[4][2];
            const int cB = 2 * ks + ((lane >> 3) & 1);
#pragma unroll
            for (int p = 0; p < 2; p++) {
                const int rowB = ((lane >> 4) & 1) * 8 + (lane & 7) + p * 16;
                LDSM_X4(bf[2 * p][0], bf[2 * p][1], bf[2 * p + 1][0], bf[2 * p + 1][1],
                        kbuf + (uint32_t)rowB * 128 + (((cB ^ (rowB & 7))) << 4));
            }
#pragma unroll
            for (int mt = 0; mt < 2; mt++)
#pragma unroll
                for (int nt = 0; nt < 4; nt++)
                    mma_f16(sc[mt][nt], qa[mt][ks], bf[nt]);
        }

        // ---- mask + online softmax (probs left in sc) ----
#pragma unroll
        for (int mt = 0; mt < 2; mt++) {
            const int qr0 = q0 + mt * 16 + g;
            const int qr1 = qr0 + 8;
            float mx0 = -1e30f, mx1 = -1e30f;
#pragma unroll
            for (int nt = 0; nt < 4; nt++) {
                const int k0c = kb + nt * 8 + 2 * t;
                const int k1c = k0c + 1;
                float s0 = sc[mt][nt][0] * 0.125f;
                float s1 = sc[mt][nt][1] * 0.125f;
                float s2 = sc[mt][nt][2] * 0.125f;
                float s3 = sc[mt][nt][3] * 0.125f;
                s0 = (k0c <= qr0 && qr0 - k0c < WIN) ? s0 : -1e30f;
                s1 = (k1c <= qr0 && qr0 - k1c < WIN) ? s1 : -1e30f;
                s2 = (k0c <= qr1 && qr1 - k0c < WIN) ? s2 : -1e30f;
                s3 = (k1c <= qr1 && qr1 - k1c < WIN) ? s3 : -1e30f;
                sc[mt][nt][0] = s0; sc[mt][nt][1] = s1;
                sc[mt][nt][2] = s2; sc[mt][nt][3] = s3;
                mx0 = fmaxf(mx0, fmaxf(s0, s1));
                mx1 = fmaxf(mx1, fmaxf(s2, s3));
            }
            mx0 = fmaxf(mx0, __shfl_xor_sync(0xFFFFFFFFu, mx0, 1));
            mx0 = fmaxf(mx0, __shfl_xor_sync(0xFFFFFFFFu, mx0, 2));
            mx1 = fmaxf(mx1, __shfl_xor_sync(0xFFFFFFFFu, mx1, 1));
            mx1 = fmaxf(mx1, __shfl_xor_sync(0xFFFFFFFFu, mx1, 2));

            const float mn0 = fmaxf(m[mt][0], mx0);
            const float mn1 = fmaxf(m[mt][1], mx1);
            const float r0 = __expf(m[mt][0] - mn0);
            const float r1 = __expf(m[mt][1] - mn1);
            m[mt][0] = mn0; m[mt][1] = mn1;
            l[mt][0] *= r0; l[mt][1] *= r1;
#pragma unroll
            for (int nt = 0; nt < 8; nt++) {
                o[mt][nt][0] *= r0; o[mt][nt][1] *= r0;
                o[mt][nt][2] *= r1; o[mt][nt][3] *= r1;
            }
#pragma unroll
            for (int nt = 0; nt < 4; nt++) {
                float p0 = __expf(sc[mt][nt][0] - mn0);
                float p1 = __expf(sc[mt][nt][1] - mn0);
                float p2 = __expf(sc[mt][nt][2] - mn1);
                float p3 = __expf(sc[mt][nt][3] - mn1);
                l[mt][0] += p0 + p1;
                l[mt][1] += p2 + p3;
                sc[mt][nt][0] = p0; sc[mt][nt][1] = p1;
                sc[mt][nt][2] = p2; sc[mt][nt][3] = p3;
            }
        }

        // ---- PV: P (regs) x V (smem, ldmatrix.trans) ----
#pragma unroll
        for (int pk = 0; pk < 2; pk++) {
            unsigned pa[2][4];
#pragma unroll
            for (int mt = 0; mt < 2; mt++) {
                pa[mt][0] = pack_h2(sc[mt][2 * pk][0],     sc[mt][2 * pk][1]);
                pa[mt][1] = pack_h2(sc[mt][2 * pk][2],     sc[mt][2 * pk][3]);
                pa[mt][2] = pack_h2(sc[mt][2 * pk + 1][0], sc[mt][2 * pk + 1][1]);
                pa[mt][3] = pack_h2(sc[mt][2 * pk + 1][2], sc[mt][2 * pk + 1][3]);
            }
            const int rowV = pk * 16 + (lane & 15);
            const uint32_t vrow = vbuf + (uint32_t)rowV * 128;
            const int swV = rowV & 7;
#pragma unroll
            for (int nt = 0; nt < 8; nt++) {
                unsigned bv[2];
                LDSM_X2T(bv[0], bv[1], vrow + (((nt ^ swV)) << 4));
#pragma unroll
                for (int mt = 0; mt < 2; mt++)
                    mma_f16(o[mt][nt], pa[mt], bv);
            }
        }
    }

    // ---- finalize ----
#pragma unroll
    for (int mt = 0; mt < 2; mt++) {
        float l0 = l[mt][0], l1 = l[mt][1];
        l0 += __shfl_xor_sync(0xFFFFFFFFu, l0, 1);
        l0 += __shfl_xor_sync(0xFFFFFFFFu, l0, 2);
        l1 += __shfl_xor_sync(0xFFFFFFFFu, l1, 1);
        l1 += __shfl_xor_sync(0xFFFFFFFFu, l1, 2);
        const float inv0 = 1.0f / (l0 + __expf(sink - m[mt][0]));
        const float inv1 = 1.0f / (l1 + __expf(sink - m[mt][1]));

        const int qr0 = q0 + mt * 16 + g;
        __half* orow0 = out + ((size_t)(b * SEQ + qr0)) * (NH * HD) + (hk * GQA + wid) * HD;
        __half* orow1 = orow0 + (size_t)8 * (NH * HD);
#pragma unroll
        for (int nt = 0; nt < 8; nt++) {
            *(unsigned*)(orow0 + nt * 8 + 2 * t) = pack_h2(o[mt][nt][0] * inv0, o[mt][nt][1] * inv0);
            *(unsigned*)(orow1 + nt * 8 + 2 * t) = pack_h2(o[mt][nt][2] * inv1, o[mt][nt][3] * inv1);
        }
    }
}

// ---------------------------------------------------------------------------
// kernel_launch
// ---------------------------------------------------------------------------
extern "C" void kernel_launch(void* const* d_in, const int* in_sizes, int n_in,
                              void* d_out, int out_size)
{
    const float* x    = (const float*)d_in[0];
    const float* Wq   = (const float*)d_in[1];
    const float* bq   = (const float*)d_in[2];
    const float* Wk   = (const float*)d_in[3];
    const float* bk   = (const float*)d_in[4];
    const float* Wv   = (const float*)d_in[5];
    const float* bv   = (const float*)d_in[6];
    const float* Wo   = (const float*)d_in[7];
    const float* bo   = (const float*)d_in[8];
    const float* sinks = (const float*)d_in[9];
    float* out = (float*)d_out;

    __half* qkvh = nullptr;
    __half* attnh = nullptr;
    cudaGetSymbolAddress((void**)&qkvh, g_qkvh);
    cudaGetSymbolAddress((void**)&attnh, g_attnh);

    static bool attr_set = false;
    if (!attr_set) {
        cudaFuncSetAttribute(gemm_qkv, cudaFuncAttributeMaxDynamicSharedMemorySize, GEMM_SMEM);
        cudaFuncSetAttribute(gemm_out, cudaFuncAttributeMaxDynamicSharedMemorySize, GEMM_SMEM);
        attr_set = true;
    }

    const int M = BATCH * SEQ;   // 2048

    // fp32 -> fp16 conversion
    cvt_kernel<<<CVT_TOTAL4 / 256, 256>>>(x, Wq, Wk, Wv, Wo);

    // Merged QKV projection -> fp16
    {
        dim3 grid(40, M / 128);
        gemm_qkv<<<grid, 512, GEMM_SMEM>>>(bq, bk, bv);
    }

    // Attention (fully fp16)
    {
        dim3 grid(SEQ / 32, NHK, BATCH);
        attn_h_kernel<<<grid, 256>>>(qkvh, sinks, attnh);
    }

    // Output projection
    {
        dim3 grid(DM / 128, M / 128);
        gemm_out<<<grid, 512, GEMM_SMEM>>>(bo, out);
    }
}